// round 6
// baseline (speedup 1.0000x reference)
#include <cuda_runtime.h>
#include <stdint.h>

// Hybrid_Conv2d via warp-level mma.sync tf32 implicit GEMM.
// out[b] = conv2d(x[b], W0 + cov[b]*W1), 3x3 pad 1, B=32, C=64, 128x128.
//
// R5: shift-reuse of the kx taps + m=32 per warp.
//  - CTA = (batch b, 2 image rows). 8 warps; warp = 32 px x 64 cout.
//  - 6 stages = (ky 0..2) x (ci-half 0..1). Each stage loads input
//    [32 ci][2 rows][130 cols] (halo'd) ONCE; 3 compute passes (kx=0,1,2)
//    read it with a one-column shift. Weights for all 3 kx staged together.
//  - SA stride 264 (mod 32 == 8) and SB stride 72: conflict-free fragment
//    loads (banks = ti*8+g, all 32 distinct).

#define HW_   128
#define C_    64
#define B_    32
#define NT    256

#define SA_STRIDE 264                    // floats per ci row (260 used)
#define SA_ELEMS  (32 * SA_STRIDE)       // 8448
#define SB_STRIDE 72
#define SB_ELEMS  (3 * 32 * SB_STRIDE)   // 6912
#define SMEM_BYTES ((SA_ELEMS + SB_ELEMS) * 4)   // 61440

__device__ uint32_t d_Wc[B_ * 9 * C_ * C_];   // [b][tap][ci][co], tf32 bits

static __device__ __forceinline__ uint32_t f2tf32(float f) {
    uint32_t r;
    asm("cvt.rna.tf32.f32 %0, %1;" : "=r"(r) : "f"(f));
    return r;
}

__global__ void build_weights_kernel(const float* __restrict__ W0,
                                     const float* __restrict__ W1,
                                     const float* __restrict__ cov) {
    const int off = blockIdx.x;        // tap 0..8
    const int b   = blockIdx.y;
    const float cv = cov[b];
    for (int i = threadIdx.x; i < C_ * C_; i += NT) {
        const int ci = i >> 6, co = i & 63;
        const int g = (co * C_ + ci) * 9 + off;
        d_Wc[((b * 9 + off) * C_ + ci) * C_ + co] = f2tf32(W0[g] + cv * W1[g]);
    }
}

extern __shared__ uint32_t smem_dyn[];

__global__ __launch_bounds__(NT, 2)
void hybrid_conv_mma_kernel(const float* __restrict__ x,
                            float* __restrict__ out) {
    const int tid = threadIdx.x;
    const int y0  = blockIdx.x * 2;    // first of 2 image rows
    const int b   = blockIdx.y;
    const int wa  = tid >> 5;          // warp 0..7
    const int lid = tid & 31;
    const int g   = lid >> 2;          // groupID 0..7
    const int ti  = lid & 3;           // thread-in-group 0..3

    uint32_t* sA = smem_dyn;                 // [32 ci][SA_STRIDE]
    uint32_t* sB = smem_dyn + SA_ELEMS;      // [3 kx][32 ci][SB_STRIDE]

    float acc[2][8][4];
    #pragma unroll
    for (int mt = 0; mt < 2; mt++)
        #pragma unroll
        for (int nt = 0; nt < 8; nt++)
            #pragma unroll
            for (int r = 0; r < 4; r++) acc[mt][nt][r] = 0.0f;

    // warp's pixel base within sA cells: row (wa>=4 -> 1), col (wa&3)*32
    const int pbase0 = (wa >> 2) * 130 + (wa & 3) * 32;

    for (int st = 0; st < 6; st++) {
        const int ky  = st >> 1;           // 0..2
        const int ci0 = (st & 1) * 32;

        __syncthreads();   // protect previous stage's data until compute done

        // ---- stage A: [32 ci][2 rows][130 cols], halo'd, tf32 ----
        {
            const int gy_lo = y0 + ky - 1;     // input row for output row y0
            for (int e = tid; e < 32 * 260; e += NT) {
                const int ci  = e / 260;
                const int pos = e - ci * 260;
                const int r   = pos / 130;
                const int c   = pos - r * 130;
                const int gy  = gy_lo + r;
                const int gx  = c - 1;
                float v = 0.0f;
                if (((unsigned)gy < (unsigned)HW_) & ((unsigned)gx < (unsigned)HW_))
                    v = x[(((size_t)(b * C_ + ci0 + ci) * HW_) + gy) * HW_ + gx];
                sA[ci * SA_STRIDE + pos] = f2tf32(v);
            }
        }

        // ---- stage B: weights for 3 kx taps, [kx][32 ci][64 co] ----
        {
            const uint32_t* wsrc = &d_Wc[((b * 9 + ky * 3) * C_ + ci0) * C_];
            #pragma unroll
            for (int i = 0; i < 24; i++) {
                const int e  = i * NT + tid;         // 0..6143
                const int kx = e >> 11;
                const int rm = e & 2047;
                const int ci = rm >> 6, co = rm & 63;
                // wsrc stride per kx: skip to next tap = 64*64 elems, but ci0
                // offset already applied; tap kx at +kx*C_*C_ only when ci0==0
                // -> index explicitly:
                sB[(kx * 32 + ci) * SB_STRIDE + co] =
                    d_Wc[((b * 9 + ky * 3 + kx) * C_ + ci0 + ci) * C_ + co];
            }
            (void)wsrc;
        }

        __syncthreads();

        // ---- compute: 3 kx passes x 4 k-steps x (2 m-tiles x 8 n-tiles) ----
        #pragma unroll
        for (int kx = 0; kx < 3; kx++) {
            const uint32_t* sBk = sB + kx * 32 * SB_STRIDE;
            const int pb = pbase0 + kx + g;
            #pragma unroll
            for (int ks = 0; ks < 4; ks++) {
                const int k = ks * 8;
                uint32_t a[2][4];
                #pragma unroll
                for (int mt = 0; mt < 2; mt++) {
                    const int p = pb + mt * 16;
                    a[mt][0] = sA[(k + ti) * SA_STRIDE + p];
                    a[mt][1] = sA[(k + ti) * SA_STRIDE + p + 8];
                    a[mt][2] = sA[(k + ti + 4) * SA_STRIDE + p];
                    a[mt][3] = sA[(k + ti + 4) * SA_STRIDE + p + 8];
                }
                #pragma unroll
                for (int nt = 0; nt < 8; nt++) {
                    const uint32_t b0 = sBk[(k + ti) * SB_STRIDE + nt * 8 + g];
                    const uint32_t b1 = sBk[(k + ti + 4) * SB_STRIDE + nt * 8 + g];
                    #pragma unroll
                    for (int mt = 0; mt < 2; mt++) {
                        asm volatile(
                            "mma.sync.aligned.m16n8k8.row.col.f32.tf32.tf32.f32 "
                            "{%0,%1,%2,%3}, {%4,%5,%6,%7}, {%8,%9}, {%0,%1,%2,%3};"
                            : "+f"(acc[mt][nt][0]), "+f"(acc[mt][nt][1]),
                              "+f"(acc[mt][nt][2]), "+f"(acc[mt][nt][3])
                            : "r"(a[mt][0]), "r"(a[mt][1]), "r"(a[mt][2]),
                              "r"(a[mt][3]), "r"(b0), "r"(b1));
                    }
                }
            }
        }
    }

    // ---- epilogue: acc -> out[b][co][y][px] ----
    #pragma unroll
    for (int mt = 0; mt < 2; mt++) {
        const int m0 = wa * 32 + mt * 16 + g;     // global px in CTA (0..255)
        const int r  = m0 >> 7;                   // image row offset 0/1
        const int c  = m0 & 127;                  // image col
        #pragma unroll
        for (int nt = 0; nt < 8; nt++) {
            const int n = nt * 8 + 2 * ti;        // cout
            float* op = out + (((size_t)(b * C_ + n) * HW_) + y0 + r) * HW_;
            op[c]                     = acc[mt][nt][0];
            op[HW_ * HW_ + c]         = acc[mt][nt][1];   // cout n+1
            op[c + 8]                 = acc[mt][nt][2];
            op[HW_ * HW_ + c + 8]     = acc[mt][nt][3];
        }
    }
}

extern "C" void kernel_launch(void* const* d_in, const int* in_sizes, int n_in,
                              void* d_out, int out_size) {
    (void)in_sizes; (void)n_in; (void)out_size;
    const float* x   = (const float*)d_in[0];
    const float* cov = (const float*)d_in[1];
    const float* W0  = (const float*)d_in[2];
    const float* W1  = (const float*)d_in[3];
    float* out = (float*)d_out;

    build_weights_kernel<<<dim3(9, B_), NT>>>(W0, W1, cov);

    cudaFuncSetAttribute(hybrid_conv_mma_kernel,
                         cudaFuncAttributeMaxDynamicSharedMemorySize, SMEM_BYTES);
    hybrid_conv_mma_kernel<<<dim3(HW_ / 2, B_), NT, SMEM_BYTES>>>(x, out);
}

// round 9
// speedup vs baseline: 1.6630x; 1.6630x over previous
#include <cuda_runtime.h>
#include <cuda_fp16.h>
#include <stdint.h>

// Hybrid_Conv2d via warp-level mma.sync fp16 (m16n8k16) implicit GEMM.
// out[b] = conv2d(x[b], W0 + cov[b]*W1), 3x3 pad 1, B=32, C=64, 128x128.
//
// R6: fp16 k16 MMA (same 10-bit mantissa as tf32, 2x K per instr) +
//     shift-reuse staging (6 stages = ky x ci-half; 3 kx passes/stage) +
//     double-buffered pipeline + hoisted staging index math.
//  - CTA = (batch b, 2 image rows), 8 warps, warp = 32 px x 64 cout.
//  - sA: [16 kw][260 pos] fp16x2 words (2 ci per word), stride 264.
//  - sB: [3 kx][16 kw][64 co] fp16x2 words, stride 72.
//  - Strides mod 32 == 8 -> fragment loads hit banks ti*8+g, all distinct.

#define HW_   128
#define C_    64
#define B_    32
#define NT    256

#define SA_STRIDE 264
#define SA_WORDS  (16 * SA_STRIDE)      // 4224
#define SB_STRIDE 72
#define SB_WORDS  (3 * 16 * SB_STRIDE)  // 3456
#define BUF_WORDS (SA_WORDS + SB_WORDS) // 7680
#define SMEM_BYTES (2 * BUF_WORDS * 4)  // 61440

// packed weights: [b][tap][ciw(32)][co(64)], fp16x2 over (ci even, ci odd)
__device__ uint32_t d_Wcp[B_ * 9 * 32 * C_];

static __device__ __forceinline__ uint32_t packh2(float lo, float hi) {
    __half2 h = __floats2half2_rn(lo, hi);   // .x = lo (low half = lower k)
    return *reinterpret_cast<uint32_t*>(&h);
}

__global__ void build_weights_kernel(const float* __restrict__ W0,
                                     const float* __restrict__ W1,
                                     const float* __restrict__ cov) {
    const int off = blockIdx.x;        // tap 0..8
    const int b   = blockIdx.y;
    const float cv = cov[b];
    for (int i = threadIdx.x; i < 32 * C_; i += NT) {
        const int ciw = i >> 6, co = i & 63;
        const int g0 = (co * C_ + 2 * ciw) * 9 + off;
        const float wlo = W0[g0] + cv * W1[g0];
        const float whi = W0[g0 + 9] + cv * W1[g0 + 9];
        d_Wcp[((b * 9 + off) * 32 + ciw) * C_ + co] = packh2(wlo, whi);
    }
}

extern __shared__ uint32_t smem_dyn[];

__global__ __launch_bounds__(NT, 2)
void hybrid_conv_mma_kernel(const float* __restrict__ x,
                            float* __restrict__ out) {
    const int tid = threadIdx.x;
    const int y0  = blockIdx.x * 2;    // first of 2 image rows
    const int b   = blockIdx.y;
    const int wa  = tid >> 5;          // warp 0..7
    const int lid = tid & 31;
    const int g   = lid >> 2;          // groupID 0..7
    const int ti  = lid & 3;           // thread-in-group 0..3

    float acc[2][8][4];
    #pragma unroll
    for (int mt = 0; mt < 2; mt++)
        #pragma unroll
        for (int nt = 0; nt < 8; nt++)
            #pragma unroll
            for (int r = 0; r < 4; r++) acc[mt][nt][r] = 0.0f;

    // warp's pixel base inside sA positions: row (wa>=4), col (wa&3)*32
    const int pbase0 = (wa >> 2) * 130 + (wa & 3) * 32;

    // ---- hoisted staging-A geometry (stage-invariant) ----
    // positions p in {tid, tid+256}, p < 260; r=p/130, c=p%130, gx=c-1
    const int pA     = tid;                 // always < 260
    const int rA     = pA / 130;
    const int cA     = pA - rA * 130;
    const int gxA    = cA - 1;
    const bool gxokA = (unsigned)gxA < (unsigned)HW_;
    const bool act2  = (tid + NT) < 260;    // second position (threads 0..3)
    const int pA2    = tid + NT;
    const int rA2    = 1;                   // 256..259 -> row 1
    const int gxA2   = (pA2 - 130) - 1;     // cols 126..129 -> gx 125..128
    const bool gxok2 = (unsigned)gxA2 < (unsigned)HW_;

    // ---- stage: fill buffer for iteration it ----
    auto stage = [&](int it, uint32_t* buf) {
        const int ky  = it >> 1;
        const int ci0 = (it & 1) * 32;
        uint32_t* sA = buf;
        // position 1
        {
            const int gy = y0 + ky - 1 + rA;
            const bool ok = gxokA & ((unsigned)gy < (unsigned)HW_);
            const float* src = x + (((size_t)(b * C_ + ci0) * HW_)
                               + (ok ? gy : 0)) * HW_ + (ok ? gxA : 0);
            #pragma unroll
            for (int j = 0; j < 16; j++) {
                float v0 = 0.f, v1 = 0.f;
                if (ok) {
                    v0 = src[(size_t)(2 * j) * (HW_ * HW_)];
                    v1 = src[(size_t)(2 * j + 1) * (HW_ * HW_)];
                }
                sA[j * SA_STRIDE + pA] = packh2(v0, v1);
            }
        }
        // position 2 (threads 0..3 only)
        if (act2) {
            const int gy = y0 + ky - 1 + rA2;
            const bool ok = gxok2 & ((unsigned)gy < (unsigned)HW_);
            const float* src = x + (((size_t)(b * C_ + ci0) * HW_)
                               + (ok ? gy : 0)) * HW_ + (ok ? gxA2 : 0);
            #pragma unroll
            for (int j = 0; j < 16; j++) {
                float v0 = 0.f, v1 = 0.f;
                if (ok) {
                    v0 = src[(size_t)(2 * j) * (HW_ * HW_)];
                    v1 = src[(size_t)(2 * j + 1) * (HW_ * HW_)];
                }
                sA[j * SA_STRIDE + pA2] = packh2(v0, v1);
            }
        }
        // weights: 3 kx taps x 16 ciw x 64 co = 3072 words, 12/thread
        uint32_t* sB = buf + SA_WORDS;
        const int ci0w = (it & 1) * 16;
        const uint32_t* wsrc = &d_Wcp[((b * 9 + ky * 3) * 32 + ci0w) * C_];
        #pragma unroll
        for (int i = 0; i < 12; i++) {
            const int e  = i * NT + tid;       // 0..3071
            const int kx = e >> 10;
            const int rm = e & 1023;
            const int ciw = rm >> 6, co = rm & 63;
            sB[(kx * 16 + ciw) * SB_STRIDE + co] =
                wsrc[(kx * 32 + ciw) * C_ + co];
        }
    };

    // ---- compute: 3 kx x 2 k-steps x (2 m-tiles x 8 n-tiles) ----
    auto compute = [&](const uint32_t* buf) {
        const uint32_t* sA = buf;
        const uint32_t* sB = buf + SA_WORDS;
        #pragma unroll
        for (int kx = 0; kx < 3; kx++) {
            const uint32_t* sBk = sB + kx * 16 * SB_STRIDE;
            const int pb = pbase0 + kx + g;
            #pragma unroll
            for (int ks = 0; ks < 2; ks++) {
                const int kb = ks * 8;
                uint32_t a[2][4];
                #pragma unroll
                for (int mt = 0; mt < 2; mt++) {
                    const int p = pb + mt * 16;
                    a[mt][0] = sA[(kb + ti) * SA_STRIDE + p];
                    a[mt][1] = sA[(kb + ti) * SA_STRIDE + p + 8];
                    a[mt][2] = sA[(kb + ti + 4) * SA_STRIDE + p];
                    a[mt][3] = sA[(kb + ti + 4) * SA_STRIDE + p + 8];
                }
                #pragma unroll
                for (int nt = 0; nt < 8; nt++) {
                    const uint32_t b0 = sBk[(kb + ti) * SB_STRIDE + nt * 8 + g];
                    const uint32_t b1 = sBk[(kb + ti + 4) * SB_STRIDE + nt * 8 + g];
                    #pragma unroll
                    for (int mt = 0; mt < 2; mt++) {
                        asm volatile(
                            "mma.sync.aligned.m16n8k16.row.col.f32.f16.f16.f32 "
                            "{%0,%1,%2,%3}, {%4,%5,%6,%7}, {%8,%9}, {%0,%1,%2,%3};"
                            : "+f"(acc[mt][nt][0]), "+f"(acc[mt][nt][1]),
                              "+f"(acc[mt][nt][2]), "+f"(acc[mt][nt][3])
                            : "r"(a[mt][0]), "r"(a[mt][1]), "r"(a[mt][2]),
                              "r"(a[mt][3]), "r"(b0), "r"(b1));
                    }
                }
            }
        }
    };

    stage(0, smem_dyn);
    for (int it = 0; it < 6; it++) {
        __syncthreads();
        if (it < 5) stage(it + 1, smem_dyn + ((it + 1) & 1) * BUF_WORDS);
        compute(smem_dyn + (it & 1) * BUF_WORDS);
    }

    // ---- epilogue: acc -> out[b][co][y][px] ----
    #pragma unroll
    for (int mt = 0; mt < 2; mt++) {
        const int m0 = wa * 32 + mt * 16 + g;     // px in CTA (0..255)
        const int r  = m0 >> 7;
        const int c  = m0 & 127;
        #pragma unroll
        for (int nt = 0; nt < 8; nt++) {
            const int n = nt * 8 + 2 * ti;        // cout
            float* op = out + (((size_t)(b * C_ + n) * HW_) + y0 + r) * HW_;
            op[c]                 = acc[mt][nt][0];
            op[HW_ * HW_ + c]     = acc[mt][nt][1];   // cout n+1
            op[c + 8]             = acc[mt][nt][2];
            op[HW_ * HW_ + c + 8] = acc[mt][nt][3];
        }
    }
}

extern "C" void kernel_launch(void* const* d_in, const int* in_sizes, int n_in,
                              void* d_out, int out_size) {
    (void)in_sizes; (void)n_in; (void)out_size;
    const float* x   = (const float*)d_in[0];
    const float* cov = (const float*)d_in[1];
    const float* W0  = (const float*)d_in[2];
    const float* W1  = (const float*)d_in[3];
    float* out = (float*)d_out;

    build_weights_kernel<<<dim3(9, B_), NT>>>(W0, W1, cov);

    cudaFuncSetAttribute(hybrid_conv_mma_kernel,
                         cudaFuncAttributeMaxDynamicSharedMemorySize, SMEM_BYTES);
    hybrid_conv_mma_kernel<<<dim3(HW_ / 2, B_), NT, SMEM_BYTES>>>(x, out);
}

// round 10
// speedup vs baseline: 2.2489x; 1.3523x over previous
#include <cuda_runtime.h>
#include <cuda_fp16.h>
#include <stdint.h>

// Hybrid_Conv2d via warp-level mma.sync fp16 (m16n8k16) implicit GEMM.
// out[b] = conv2d(x[b], W0 + cov[b]*W1), 3x3 pad 1, B=32, C=64, 128x128.
//
// R9: channels-last fp16 x (prologue transpose) + cp.async staging +
//     single-stage SMEM slab (6 halo rows, all ci; all 9 taps of weights) +
//     m64 x n64 register tile per warp (1.0 LDS/MMA), 1 CTA/SM.
//  - CTA = (batch b, 4 image rows), 8 warps: warp = 64 px x 64 cout.
//  - sA: [780 pos][36 words] fp16x2 (ci pair 2w,2w+1); stride 36 -> banks 4g+ti.
//  - sB: [9 tap][32 kw][68 words]; stride 68 -> banks 4ti+g. Both conflict-free.

#define HW_   128
#define C_    64
#define B_    32
#define NT    256

#define SA_POS    780                 // 6 rows x 130 cols (halo'd)
#define SA_ROWB   144                 // 128B data + 16B pad per pos
#define SA_W      36                  // words per pos
#define SA_BYTES  (SA_POS * SA_ROWB)  // 112320
#define SB_ROWW   68                  // words per k-word row (64 + 4 pad)
#define SB_ROWB   (SB_ROWW * 4)       // 272
#define SB_BYTES  (9 * 32 * SB_ROWB)  // 78336
#define SMEM_BYTES (SA_BYTES + SB_BYTES)   // 190656

__device__ __half   d_xh[(size_t)B_ * HW_ * HW_ * C_];   // [b][y][x][ci]
__device__ uint32_t d_Wcp[B_ * 9 * 32 * C_];  // [b][tap][kw][co], fp16x2(ci pair)

static __device__ __forceinline__ uint32_t smem_u32(const void* p) {
    uint32_t a;
    asm("{ .reg .u64 t; cvta.to.shared.u64 t, %1; cvt.u32.u64 %0, t; }" : "=r"(a) : "l"(p));
    return a;
}
static __device__ __forceinline__ void cp16(uint32_t dst, const void* src, int sz) {
    asm volatile("cp.async.cg.shared.global [%0], [%1], 16, %2;"
                 :: "r"(dst), "l"(src), "r"(sz) : "memory");
}
static __device__ __forceinline__ uint32_t packh2(float lo, float hi) {
    __half2 h = __floats2half2_rn(lo, hi);
    return *reinterpret_cast<uint32_t*>(&h);
}

__global__ void build_weights_kernel(const float* __restrict__ W0,
                                     const float* __restrict__ W1,
                                     const float* __restrict__ cov) {
    const int off = blockIdx.x;        // tap 0..8
    const int b   = blockIdx.y;
    const float cv = cov[b];
    for (int i = threadIdx.x; i < 32 * C_; i += NT) {
        const int kw = i >> 6, co = i & 63;
        const int g0 = (co * C_ + 2 * kw) * 9 + off;
        const float wlo = W0[g0] + cv * W1[g0];
        const float whi = W0[g0 + 9] + cv * W1[g0 + 9];
        d_Wcp[((b * 9 + off) * 32 + kw) * C_ + co] = packh2(wlo, whi);
    }
}

__global__ void transpose_x_kernel(const float* __restrict__ x) {
    __shared__ float sT[C_][HW_ + 1];
    const int y = blockIdx.x, b = blockIdx.y;
    const float* src = x + ((size_t)(b * C_) * HW_ + y) * HW_;
    for (int e = threadIdx.x; e < C_ * HW_; e += NT) {
        const int ci = e >> 7, xx = e & 127;
        sT[ci][xx] = src[(size_t)ci * HW_ * HW_ + xx];
    }
    __syncthreads();
    __half* dst = d_xh + ((size_t)(b * HW_) + y) * HW_ * C_;
    for (int e = threadIdx.x; e < C_ * HW_; e += NT) {
        const int xx = e >> 6, ci = e & 63;
        dst[xx * C_ + ci] = __float2half(sT[ci][xx]);
    }
}

extern __shared__ uint32_t smem_dyn[];

__global__ __launch_bounds__(NT, 1)
void hybrid_conv_mma_kernel(float* __restrict__ out) {
    const int tid = threadIdx.x;
    const int wa  = tid >> 5;
    const int lid = tid & 31;
    const int g   = lid >> 2;
    const int ti  = lid & 3;
    const int y0  = blockIdx.x * 4;
    const int b   = blockIdx.y;

    const uint32_t sa_base = smem_u32(smem_dyn);
    const uint32_t sb_base = sa_base + SA_BYTES;

    // ---- stage A: 6 halo rows x 130 cols x 64 ci via cp.async (zfill OOB) ----
    for (int q = tid; q < SA_POS * 8; q += NT) {
        const int pos = q >> 3, ch = q & 7;
        const int r = pos / 130, c = pos - r * 130;
        const int gy = y0 - 1 + r, gx = c - 1;
        const bool ok = ((unsigned)gy < (unsigned)HW_) & ((unsigned)gx < (unsigned)HW_);
        const __half* src = d_xh + (((size_t)(b * HW_ + (ok ? gy : 0)) * HW_
                               + (ok ? gx : 0)) * C_ + ch * 8);
        cp16(sa_base + pos * SA_ROWB + ch * 16, src, ok ? 16 : 0);
    }
    // ---- stage B: all 9 taps of weights ----
    for (int q = tid; q < 9 * 32 * 16; q += NT) {
        const int row = q >> 4, ch = q & 15;     // row = tap*32 + kw
        const uint32_t* src = d_Wcp + ((size_t)(b * 9 * 32) + row) * C_ + ch * 4;
        cp16(sb_base + row * SB_ROWB + ch * 16, src, 16);
    }
    asm volatile("cp.async.commit_group;" ::: "memory");
    asm volatile("cp.async.wait_group 0;" ::: "memory");
    __syncthreads();

    float acc[4][8][4];
    #pragma unroll
    for (int mt = 0; mt < 4; mt++)
        #pragma unroll
        for (int nt = 0; nt < 8; nt++)
            #pragma unroll
            for (int r = 0; r < 4; r++) acc[mt][nt][r] = 0.0f;

    const uint32_t* sAw = smem_dyn;
    const uint32_t* sBw = smem_dyn + SA_BYTES / 4;

    // warp covers output row (wa>>1), cols (wa&1)*64 .. +64
    const int pw = (wa >> 1) * 130 + (wa & 1) * 64 + g;

    #pragma unroll 1
    for (int tap = 0; tap < 9; tap++) {
        const int ky = tap / 3;
        const int posoff = ky * 130 + (tap - ky * 3);
        const int pb = pw + posoff;
        const uint32_t* sBt = sBw + tap * 32 * SB_ROWW;
        #pragma unroll
        for (int ks = 0; ks < 4; ks++) {
            const int kb = ks * 8;
            uint32_t a[4][4];
            #pragma unroll
            for (int mt = 0; mt < 4; mt++) {
                const int p = pb + mt * 16;
                a[mt][0] = sAw[p * SA_W + kb + ti];
                a[mt][1] = sAw[(p + 8) * SA_W + kb + ti];
                a[mt][2] = sAw[p * SA_W + kb + ti + 4];
                a[mt][3] = sAw[(p + 8) * SA_W + kb + ti + 4];
            }
            #pragma unroll
            for (int nt = 0; nt < 8; nt++) {
                const uint32_t b0 = sBt[(kb + ti) * SB_ROWW + nt * 8 + g];
                const uint32_t b1 = sBt[(kb + ti + 4) * SB_ROWW + nt * 8 + g];
                #pragma unroll
                for (int mt = 0; mt < 4; mt++) {
                    asm volatile(
                        "mma.sync.aligned.m16n8k16.row.col.f32.f16.f16.f32 "
                        "{%0,%1,%2,%3}, {%4,%5,%6,%7}, {%8,%9}, {%0,%1,%2,%3};"
                        : "+f"(acc[mt][nt][0]), "+f"(acc[mt][nt][1]),
                          "+f"(acc[mt][nt][2]), "+f"(acc[mt][nt][3])
                        : "r"(a[mt][0]), "r"(a[mt][1]), "r"(a[mt][2]),
                          "r"(a[mt][3]), "r"(b0), "r"(b1));
                }
            }
        }
    }

    // ---- epilogue: acc -> out[b][co][row][col] ----
    const int row   = y0 + (wa >> 1);
    const int cbase = (wa & 1) * 64;
    #pragma unroll
    for (int mt = 0; mt < 4; mt++) {
        const int col = cbase + mt * 16 + g;
        #pragma unroll
        for (int nt = 0; nt < 8; nt++) {
            const int n = nt * 8 + 2 * ti;
            float* op = out + (((size_t)(b * C_ + n) * HW_) + row) * HW_;
            op[col]                 = acc[mt][nt][0];
            op[HW_ * HW_ + col]     = acc[mt][nt][1];   // cout n+1
            op[col + 8]             = acc[mt][nt][2];
            op[HW_ * HW_ + col + 8] = acc[mt][nt][3];
        }
    }
}

extern "C" void kernel_launch(void* const* d_in, const int* in_sizes, int n_in,
                              void* d_out, int out_size) {
    (void)in_sizes; (void)n_in; (void)out_size;
    const float* x   = (const float*)d_in[0];
    const float* cov = (const float*)d_in[1];
    const float* W0  = (const float*)d_in[2];
    const float* W1  = (const float*)d_in[3];
    float* out = (float*)d_out;

    build_weights_kernel<<<dim3(9, B_), NT>>>(W0, W1, cov);
    transpose_x_kernel<<<dim3(HW_, B_), NT>>>(x);

    cudaFuncSetAttribute(hybrid_conv_mma_kernel,
                         cudaFuncAttributeMaxDynamicSharedMemorySize, SMEM_BYTES);
    hybrid_conv_mma_kernel<<<dim3(HW_ / 4, B_), NT, SMEM_BYTES>>>(out);
}

// round 11
// speedup vs baseline: 2.3561x; 1.0477x over previous
#include <cuda_runtime.h>
#include <cuda_fp16.h>
#include <stdint.h>

// Hybrid_Conv2d via warp-level mma.sync fp16 (m16n8k16) implicit GEMM.
// out[b] = conv2d(x[b], W0 + cov[b]*W1), 3x3 pad 1, B=32, C=64, 128x128.
//
// R10: ldmatrix fragment loads (0.25 LDS-instr/MMA) + split-stage cp.async
//      overlap + fused/vectorized prologue.
//  - CTA = (batch b, 4 image rows), 8 warps: warp = 64 px x 64 cout (m64n64).
//  - sA: [780 pos][32 kw + 4 pad] fp16x2; row stride 144B -> ldmatrix rows
//    cover all 32 banks. sB: [9 tap][64 co][32 kw + pad], same stride.
//  - Stage group0 = A kw 0..15 + all B; group1 = A kw 16..31. Compute
//    ks{0,1} after wait_group 1, ks{2,3} after wait_group 0.

#define HW_   128
#define C_    64
#define B_    32
#define NT    256

#define SA_POS    780                 // 6 halo rows x 130 cols
#define ROWB      144                 // 128B data + 16B pad
#define SA_BYTES  (SA_POS * ROWB)     // 112320
#define SB_ROWS   (9 * 64)            // tap x co
#define SB_BYTES  (SB_ROWS * ROWB)    // 82944
#define SMEM_BYTES (SA_BYTES + SB_BYTES)   // 195264

__device__ __half   d_xh[(size_t)B_ * HW_ * HW_ * C_];   // [b][y][x][ci]
__device__ uint32_t d_Wcp[B_ * 9 * C_ * 32];  // [b][tap][co][kw], fp16x2(ci pair)

static __device__ __forceinline__ uint32_t smem_u32(const void* p) {
    uint32_t a;
    asm("{ .reg .u64 t; cvta.to.shared.u64 t, %1; cvt.u32.u64 %0, t; }" : "=r"(a) : "l"(p));
    return a;
}
static __device__ __forceinline__ void cp16(uint32_t dst, const void* src, int sz) {
    asm volatile("cp.async.cg.shared.global [%0], [%1], 16, %2;"
                 :: "r"(dst), "l"(src), "r"(sz) : "memory");
}
template <int N> static __device__ __forceinline__ void cp_wait() {
    asm volatile("cp.async.wait_group %0;" :: "n"(N) : "memory");
}
static __device__ __forceinline__ uint32_t packh2(float lo, float hi) {
    __half2 h = __floats2half2_rn(lo, hi);
    return *reinterpret_cast<uint32_t*>(&h);
}
#define LDSM_X4(r0, r1, r2, r3, addr)                                        \
    asm volatile("ldmatrix.sync.aligned.m8n8.x4.shared.b16 {%0,%1,%2,%3}, [%4];" \
        : "=r"(r0), "=r"(r1), "=r"(r2), "=r"(r3) : "r"(addr))

// ---- fused prologue: transpose x to channels-last fp16 + build weights ----
__global__ void prologue_kernel(const float* __restrict__ x,
                                const float* __restrict__ W0,
                                const float* __restrict__ W1,
                                const float* __restrict__ cov) {
    const int b = blockIdx.y;
    if (blockIdx.x < HW_) {
        __shared__ float sT[C_][HW_ + 1];
        const int y = blockIdx.x;
        const float4* src = (const float4*)(x + ((size_t)(b * C_) * HW_ + y) * HW_);
        for (int e = threadIdx.x; e < C_ * (HW_ / 4); e += NT) {
            const int ci = e >> 5, xq = e & 31;
            float4 v = src[(size_t)ci * (HW_ * HW_ / 4) + xq];
            sT[ci][xq * 4]     = v.x;
            sT[ci][xq * 4 + 1] = v.y;
            sT[ci][xq * 4 + 2] = v.z;
            sT[ci][xq * 4 + 3] = v.w;
        }
        __syncthreads();
        uint32_t* dst = (uint32_t*)(d_xh + ((size_t)(b * HW_) + y) * HW_ * C_);
        for (int e = threadIdx.x; e < HW_ * 32; e += NT) {
            const int xx = e >> 5, kw = e & 31;
            dst[xx * 32 + kw] = packh2(sT[2 * kw][xx], sT[2 * kw + 1][xx]);
        }
    } else {
        const int tap = blockIdx.x - HW_;     // 0..8
        const float cv = cov[b];
        for (int i = threadIdx.x; i < C_ * 32; i += NT) {
            const int co = i >> 5, kw = i & 31;
            const int g0 = (co * C_ + 2 * kw) * 9 + tap;
            d_Wcp[((b * 9 + tap) * C_ + co) * 32 + kw] =
                packh2(W0[g0] + cv * W1[g0], W0[g0 + 9] + cv * W1[g0 + 9]);
        }
    }
}

extern __shared__ uint32_t smem_dyn[];

__global__ __launch_bounds__(NT, 1)
void hybrid_conv_mma_kernel(float* __restrict__ out) {
    const int tid = threadIdx.x;
    const int wa  = tid >> 5;
    const int lid = tid & 31;
    const int g   = lid >> 2;
    const int ti  = lid & 3;
    const int y0  = blockIdx.x * 4;
    const int b   = blockIdx.y;

    const uint32_t sa_base = smem_u32(smem_dyn);
    const uint32_t sb_base = sa_base + SA_BYTES;

    // ---- group0: A kw 0..15 (ch 0..3) + all B ----
    for (int q = tid; q < SA_POS * 4; q += NT) {
        const int pos = q >> 2, ch = q & 3;
        const int r = pos / 130, c = pos - r * 130;
        const int gy = y0 - 1 + r, gx = c - 1;
        const bool ok = ((unsigned)gy < (unsigned)HW_) & ((unsigned)gx < (unsigned)HW_);
        const __half* src = d_xh + (((size_t)(b * HW_ + (ok ? gy : 0)) * HW_
                               + (ok ? gx : 0)) * C_ + ch * 8);
        cp16(sa_base + pos * ROWB + ch * 16, src, ok ? 16 : 0);
    }
    for (int q = tid; q < SB_ROWS * 8; q += NT) {
        const int row = q >> 3, ch = q & 7;
        cp16(sb_base + row * ROWB + ch * 16,
             d_Wcp + ((size_t)(b * SB_ROWS) + row) * 32 + ch * 4, 16);
    }
    asm volatile("cp.async.commit_group;" ::: "memory");
    // ---- group1: A kw 16..31 (ch 4..7) ----
    for (int q = tid; q < SA_POS * 4; q += NT) {
        const int pos = q >> 2, ch = (q & 3) + 4;
        const int r = pos / 130, c = pos - r * 130;
        const int gy = y0 - 1 + r, gx = c - 1;
        const bool ok = ((unsigned)gy < (unsigned)HW_) & ((unsigned)gx < (unsigned)HW_);
        const __half* src = d_xh + (((size_t)(b * HW_ + (ok ? gy : 0)) * HW_
                               + (ok ? gx : 0)) * C_ + ch * 8);
        cp16(sa_base + pos * ROWB + ch * 16, src, ok ? 16 : 0);
    }
    asm volatile("cp.async.commit_group;" ::: "memory");

    float acc[4][8][4];
    #pragma unroll
    for (int mt = 0; mt < 4; mt++)
        #pragma unroll
        for (int nt = 0; nt < 8; nt++)
            #pragma unroll
            for (int r = 0; r < 4; r++) acc[mt][nt][r] = 0.0f;

    // per-lane ldmatrix address components
    const int pwarp  = (wa >> 1) * 130 + (wa & 1) * 64;
    const uint32_t laneA  = (uint32_t)((lid & 15) * ROWB + ((lid & 16) ? 16 : 0));
    const int      laneBc = (lid & 7) + ((lid >> 4) << 3);
    const uint32_t laneBk = (lid & 8) ? 16u : 0u;

    #pragma unroll
    for (int half = 0; half < 2; half++) {
        if (half == 0) cp_wait<1>(); else cp_wait<0>();
        __syncthreads();

        #pragma unroll 1
        for (int tap = 0; tap < 9; tap++) {
            const int ky = tap / 3;
            const int pb = pwarp + ky * 130 + (tap - ky * 3);
            const uint32_t sbt = sb_base + (uint32_t)(tap * 64 * ROWB);
            #pragma unroll
            for (int ks2 = 0; ks2 < 2; ks2++) {
                const uint32_t kbyte = (uint32_t)((half * 2 + ks2) * 32);
                uint32_t a[4][4];
                #pragma unroll
                for (int mt = 0; mt < 4; mt++) {
                    const uint32_t ad = sa_base
                        + (uint32_t)((pb + mt * 16) * ROWB) + kbyte + laneA;
                    LDSM_X4(a[mt][0], a[mt][1], a[mt][2], a[mt][3], ad);
                }
                #pragma unroll
                for (int q = 0; q < 4; q++) {
                    uint32_t b0, b1, b2, b3;
                    const uint32_t bd = sbt
                        + (uint32_t)((16 * q + laneBc) * ROWB) + kbyte + laneBk;
                    LDSM_X4(b0, b1, b2, b3, bd);
                    #pragma unroll
                    for (int mt = 0; mt < 4; mt++) {
                        asm volatile(
                            "mma.sync.aligned.m16n8k16.row.col.f32.f16.f16.f32 "
                            "{%0,%1,%2,%3}, {%4,%5,%6,%7}, {%8,%9}, {%0,%1,%2,%3};"
                            : "+f"(acc[mt][2 * q][0]), "+f"(acc[mt][2 * q][1]),
                              "+f"(acc[mt][2 * q][2]), "+f"(acc[mt][2 * q][3])
                            : "r"(a[mt][0]), "r"(a[mt][1]), "r"(a[mt][2]),
                              "r"(a[mt][3]), "r"(b0), "r"(b1));
                    }
                    #pragma unroll
                    for (int mt = 0; mt < 4; mt++) {
                        asm volatile(
                            "mma.sync.aligned.m16n8k16.row.col.f32.f16.f16.f32 "
                            "{%0,%1,%2,%3}, {%4,%5,%6,%7}, {%8,%9}, {%0,%1,%2,%3};"
                            : "+f"(acc[mt][2 * q + 1][0]), "+f"(acc[mt][2 * q + 1][1]),
                              "+f"(acc[mt][2 * q + 1][2]), "+f"(acc[mt][2 * q + 1][3])
                            : "r"(a[mt][0]), "r"(a[mt][1]), "r"(a[mt][2]),
                              "r"(a[mt][3]), "r"(b2), "r"(b3));
                    }
                }
            }
        }
    }

    // ---- epilogue: acc -> out[b][co][row][col] ----
    const int row   = y0 + (wa >> 1);
    const int cbase = (wa & 1) * 64;
    #pragma unroll
    for (int mt = 0; mt < 4; mt++) {
        const int col = cbase + mt * 16 + g;
        #pragma unroll
        for (int nt = 0; nt < 8; nt++) {
            const int n = nt * 8 + 2 * ti;
            float* op = out + (((size_t)(b * C_ + n) * HW_) + row) * HW_;
            op[col]                 = acc[mt][nt][0];
            op[HW_ * HW_ + col]     = acc[mt][nt][1];   // cout n+1
            op[col + 8]             = acc[mt][nt][2];
            op[HW_ * HW_ + col + 8] = acc[mt][nt][3];
        }
    }
}

extern "C" void kernel_launch(void* const* d_in, const int* in_sizes, int n_in,
                              void* d_out, int out_size) {
    (void)in_sizes; (void)n_in; (void)out_size;
    const float* x   = (const float*)d_in[0];
    const float* cov = (const float*)d_in[1];
    const float* W0  = (const float*)d_in[2];
    const float* W1  = (const float*)d_in[3];
    float* out = (float*)d_out;

    prologue_kernel<<<dim3(HW_ + 9, B_), NT>>>(x, W0, W1, cov);

    cudaFuncSetAttribute(hybrid_conv_mma_kernel,
                         cudaFuncAttributeMaxDynamicSharedMemorySize, SMEM_BYTES);
    hybrid_conv_mma_kernel<<<dim3(HW_ / 4, B_), NT, SMEM_BYTES>>>(out);
}